// round 1
// baseline (speedup 1.0000x reference)
#include <cuda_runtime.h>
#include <math.h>

#define DDIM 2048
#define NROWS 65536
#define CHUNKS 512
#define RPC (NROWS / CHUNKS)      // 128 rows per chunk
#define ALIGN_BLKS 64
#define ALIGN_ROWS (DDIM / ALIGN_BLKS)  // 32

// -------- device scratch (no allocations allowed) --------
__device__ float g_align_part[ALIGN_BLKS][2][DDIM];  // 1 MB
__device__ float g_align[2][DDIM];
__device__ float g_acc[2][CHUNKS][DDIM];             // 8 MB
__device__ float g_m[2][CHUNKS];
__device__ float g_z[2][CHUNKS];
__device__ float g_M[2];
__device__ float g_Z[2];

// ---------------------------------------------------------
// Kernel 1: partial GEMV for both sides against shared W_a.
// Block b handles rows [b*32, b*32+32). 256 threads, thread t
// owns columns {t, t+256, ..., t+1792}. Coalesced W reads.
// ---------------------------------------------------------
__global__ void align_partial(const float* __restrict__ wl,
                              const float* __restrict__ wr,
                              const float* __restrict__ Wa) {
    int b = blockIdx.x;
    int t = threadIdx.x;
    float accl[8], accr[8];
#pragma unroll
    for (int k = 0; k < 8; k++) { accl[k] = 0.f; accr[k] = 0.f; }

    int r0 = b * ALIGN_ROWS;
    for (int i = 0; i < ALIGN_ROWS; i++) {
        int row = r0 + i;
        float vl = wl[row];
        float vr = wr[row];
        const float* Wrow = Wa + (size_t)row * DDIM;
#pragma unroll
        for (int k = 0; k < 8; k++) {
            float w = Wrow[t + 256 * k];
            accl[k] = fmaf(vl, w, accl[k]);
            accr[k] = fmaf(vr, w, accr[k]);
        }
    }
#pragma unroll
    for (int k = 0; k < 8; k++) {
        g_align_part[b][0][t + 256 * k] = accl[k];
        g_align_part[b][1][t + 256 * k] = accr[k];
    }
}

// ---------------------------------------------------------
// Kernel 2: reduce align partials, add bias, tanh.
// grid 8 x 256 threads = 2048 columns.
// ---------------------------------------------------------
__global__ void align_finalize(const float* __restrict__ ba) {
    int j = blockIdx.x * blockDim.x + threadIdx.x;
    float bias = ba[j];
    float sl = bias, sr = bias;
    for (int b = 0; b < ALIGN_BLKS; b++) {
        sl += g_align_part[b][0][j];
        sr += g_align_part[b][1][j];
    }
    g_align[0][j] = tanhf(sl);
    g_align[1][j] = tanhf(sr);
}

// ---------------------------------------------------------
// Kernel 3: fused score + online-softmax + weighted accumulate.
// grid (CHUNKS, 2). 512 threads; thread t owns cols [4t, 4t+4).
// Candidates are read from HBM exactly once.
// ---------------------------------------------------------
__global__ void __launch_bounds__(512, 4)
attn_fused(const float* __restrict__ candL, const float* __restrict__ candR) {
    const int side  = blockIdx.y;                 // 0: left word vs candR
    const int chunk = blockIdx.x;
    const float* cand = (side == 0) ? candR : candL;
    const int t = threadIdx.x;
    const int warp = t >> 5, lane = t & 31;

    __shared__ float sh[2][16];

    // Register-cached align slice for this thread's 4 columns.
    float4 a4 = *reinterpret_cast<const float4*>(&g_align[side][4 * t]);

    float acc0 = 0.f, acc1 = 0.f, acc2 = 0.f, acc3 = 0.f;
    float m = -1e30f, Z = 0.f;

    const float4* base =
        reinterpret_cast<const float4*>(cand + (size_t)chunk * RPC * DDIM) + t;

    for (int r = 0; r < RPC; r++) {
        float4 x = base[(size_t)r * (DDIM / 4)];
        float p = x.x * a4.x + x.y * a4.y + x.z * a4.z + x.w * a4.w;

        // warp reduce
#pragma unroll
        for (int o = 16; o > 0; o >>= 1)
            p += __shfl_xor_sync(0xffffffffu, p, o);

        float* buf = sh[r & 1];
        if (lane == 0) buf[warp] = p;
        __syncthreads();

        float s = 0.f;
#pragma unroll
        for (int k = 0; k < 16; k++) s += buf[k];

        // online softmax update (uniform branch: s identical across block)
        if (s > m) {
            float c = __expf(m - s);   // m=-1e30 first time -> c==0
            Z *= c;
            acc0 *= c; acc1 *= c; acc2 *= c; acc3 *= c;
            m = s;
        }
        float w = __expf(s - m);
        Z += w;
        acc0 = fmaf(w, x.x, acc0);
        acc1 = fmaf(w, x.y, acc1);
        acc2 = fmaf(w, x.z, acc2);
        acc3 = fmaf(w, x.w, acc3);
    }

    float4 o4 = make_float4(acc0, acc1, acc2, acc3);
    *reinterpret_cast<float4*>(&g_acc[side][chunk][4 * t]) = o4;
    if (t == 0) {
        g_m[side][chunk] = m;
        g_z[side][chunk] = Z;
    }
}

// ---------------------------------------------------------
// Kernel 4: per-side global max + normalizer over chunk partials.
// grid 2 x 512 (CHUNKS == 512).
// ---------------------------------------------------------
__global__ void softmax_stats() {
    int side = blockIdx.x;
    int t = threadIdx.x;
    __shared__ float sm[CHUNKS];

    float mv = g_m[side][t];
    sm[t] = mv;
    __syncthreads();
    for (int o = 256; o > 0; o >>= 1) {
        if (t < o) sm[t] = fmaxf(sm[t], sm[t + o]);
        __syncthreads();
    }
    float M = sm[0];
    __syncthreads();

    float z = g_z[side][t] * __expf(mv - M);
    sm[t] = z;
    __syncthreads();
    for (int o = 256; o > 0; o >>= 1) {
        if (t < o) sm[t] += sm[t + o];
        __syncthreads();
    }
    if (t == 0) { g_M[side] = M; g_Z[side] = sm[0]; }
}

// ---------------------------------------------------------
// Kernel 5: combine chunk accumulators into final outputs.
// grid (8, 2), 256 threads: 256 cols per block.
// out layout: [0..2047] = left result, [2048..4095] = right.
// ---------------------------------------------------------
__global__ void combine(float* __restrict__ out) {
    int side = blockIdx.y;
    int j = blockIdx.x * 256 + threadIdx.x;

    __shared__ float coef[CHUNKS];
    float M  = g_M[side];
    float Zi = 1.0f / g_Z[side];
    for (int c = threadIdx.x; c < CHUNKS; c += 256)
        coef[c] = __expf(g_m[side][c] - M);
    __syncthreads();

    float s = 0.f;
    for (int c = 0; c < CHUNKS; c++)
        s = fmaf(coef[c], g_acc[side][c][j], s);

    out[side * DDIM + j] = s * Zi;
}

// ---------------------------------------------------------
extern "C" void kernel_launch(void* const* d_in, const int* in_sizes, int n_in,
                              void* d_out, int out_size) {
    const float* wl    = (const float*)d_in[0];  // embed_word_l  [1, D]
    const float* wr    = (const float*)d_in[1];  // embed_word_r  [1, D]
    const float* candL = (const float*)d_in[2];  // embed_candidates_l [N, D]
    const float* candR = (const float*)d_in[3];  // embed_candidates_r [N, D]
    const float* Wa    = (const float*)d_in[4];  // W_a [D, D]
    const float* ba    = (const float*)d_in[5];  // b_a [1, D]
    float* out = (float*)d_out;

    align_partial<<<ALIGN_BLKS, 256>>>(wl, wr, Wa);
    align_finalize<<<DDIM / 256, 256>>>(ba);
    attn_fused<<<dim3(CHUNKS, 2), 512>>>(candL, candR);
    softmax_stats<<<2, CHUNKS>>>();
    combine<<<dim3(DDIM / 256, 2), 256>>>(out);
}

// round 2
// speedup vs baseline: 1.3126x; 1.3126x over previous
#include <cuda_runtime.h>
#include <math.h>

#define DDIM 2048
#define NROWS 65536
#define RPB 128                       // rows per block (attn)
#define BLKS_PER_SIDE (NROWS / RPB)   // 512
#define WARPS_PB 8
#define RPW (RPB / WARPS_PB)          // 16 rows per warp-stream
#define STREAMS (BLKS_PER_SIDE * WARPS_PB)  // 4096 per side
#define SGROUPS 16
#define SG_SZ (STREAMS / SGROUPS)     // 256
#define ALIGN_BLKS 128
#define ALIGN_ROWS (DDIM / ALIGN_BLKS)  // 16

// -------- device scratch (no allocations allowed) --------
__device__ float g_align_part[ALIGN_BLKS][2][DDIM];     // 2 MB
__device__ float g_align[2][DDIM];
__device__ float g_acc[2][STREAMS][DDIM];               // 64 MB
__device__ float g_m[2][STREAMS];
__device__ float g_z[2][STREAMS];
__device__ float g_M[2];
__device__ float g_Z[2];
__device__ float g_part[2][SGROUPS][DDIM];

// ---------------------------------------------------------
// Kernel 1: partial GEMV for both sides against shared W_a.
// ---------------------------------------------------------
__global__ void align_partial(const float* __restrict__ wl,
                              const float* __restrict__ wr,
                              const float* __restrict__ Wa) {
    int b = blockIdx.x;
    int t = threadIdx.x;
    float accl[8], accr[8];
#pragma unroll
    for (int k = 0; k < 8; k++) { accl[k] = 0.f; accr[k] = 0.f; }

    int r0 = b * ALIGN_ROWS;
    for (int i = 0; i < ALIGN_ROWS; i++) {
        int row = r0 + i;
        float vl = wl[row];
        float vr = wr[row];
        const float* Wrow = Wa + (size_t)row * DDIM;
#pragma unroll
        for (int k = 0; k < 8; k++) {
            float w = Wrow[t + 256 * k];
            accl[k] = fmaf(vl, w, accl[k]);
            accr[k] = fmaf(vr, w, accr[k]);
        }
    }
#pragma unroll
    for (int k = 0; k < 8; k++) {
        g_align_part[b][0][t + 256 * k] = accl[k];
        g_align_part[b][1][t + 256 * k] = accr[k];
    }
}

// ---------------------------------------------------------
// Kernel 2: reduce align partials, add bias, tanh.
// ---------------------------------------------------------
__global__ void align_finalize(const float* __restrict__ ba) {
    int j = blockIdx.x * blockDim.x + threadIdx.x;
    float bias = ba[j];
    float sl = bias, sr = bias;
    for (int b = 0; b < ALIGN_BLKS; b++) {
        sl += g_align_part[b][0][j];
        sr += g_align_part[b][1][j];
    }
    g_align[0][j] = tanhf(sl);
    g_align[1][j] = tanhf(sr);
}

// ---------------------------------------------------------
// Kernel 3: fused score + online-softmax + weighted accumulate.
// Barrier-free streaming: each WARP owns complete rows and a
// private (m, Z, acc[2048]) online-softmax state. Lane l holds
// columns {l*4 + 128*c + 0..3 : c in 0..15}. MLP=16 per row.
// ---------------------------------------------------------
__global__ void __launch_bounds__(256, 1)
attn_fused(const float* __restrict__ candL, const float* __restrict__ candR) {
    const int side = blockIdx.y;                  // 0: left word vs candR
    const float* cand = (side == 0) ? candR : candL;
    const int blk  = blockIdx.x;
    const int warp = threadIdx.x >> 5;
    const int lane = threadIdx.x & 31;

    __shared__ float s_align[DDIM];
    for (int i = threadIdx.x; i < DDIM; i += 256)
        s_align[i] = g_align[side][i];
    __syncthreads();   // only barrier in the kernel

    const float4* al = reinterpret_cast<const float4*>(s_align) + lane;

    float4 acc[16];
#pragma unroll
    for (int c = 0; c < 16; c++) acc[c] = make_float4(0.f, 0.f, 0.f, 0.f);
    float m = -1e30f, Z = 0.f;

    const int row0 = blk * RPB + warp * RPW;

    for (int r = 0; r < RPW; r++) {
        const float4* rp =
            reinterpret_cast<const float4*>(cand + (size_t)(row0 + r) * DDIM) + lane;
        float4 x[16];
#pragma unroll
        for (int c = 0; c < 16; c++) x[c] = rp[c * 32];

        float p0 = 0.f, p1 = 0.f, p2 = 0.f, p3 = 0.f;
#pragma unroll
        for (int c = 0; c < 16; c++) {
            float4 a = al[c * 32];
            p0 = fmaf(x[c].x, a.x, p0);
            p1 = fmaf(x[c].y, a.y, p1);
            p2 = fmaf(x[c].z, a.z, p2);
            p3 = fmaf(x[c].w, a.w, p3);
        }
        float p = (p0 + p1) + (p2 + p3);
#pragma unroll
        for (int o = 16; o > 0; o >>= 1)
            p += __shfl_xor_sync(0xffffffffu, p, o);

        // warp-uniform online softmax update
        if (p > m) {
            float c = __expf(m - p);   // first row: exp(-huge) == 0
            Z *= c;
#pragma unroll
            for (int k = 0; k < 16; k++) {
                acc[k].x *= c; acc[k].y *= c; acc[k].z *= c; acc[k].w *= c;
            }
            m = p;
        }
        float w = __expf(p - m);
        Z += w;
#pragma unroll
        for (int k = 0; k < 16; k++) {
            acc[k].x = fmaf(w, x[k].x, acc[k].x);
            acc[k].y = fmaf(w, x[k].y, acc[k].y);
            acc[k].z = fmaf(w, x[k].z, acc[k].z);
            acc[k].w = fmaf(w, x[k].w, acc[k].w);
        }
    }

    const int stream = blk * WARPS_PB + warp;
    float4* op = reinterpret_cast<float4*>(&g_acc[side][stream][0]) + lane;
#pragma unroll
    for (int c = 0; c < 16; c++) op[c * 32] = acc[c];
    if (lane == 0) {
        g_m[side][stream] = m;
        g_z[side][stream] = Z;
    }
}

// ---------------------------------------------------------
// Kernel 4: per-side global max + normalizer over stream partials.
// ---------------------------------------------------------
__global__ void softmax_stats() {
    const int side = blockIdx.x;
    const int t = threadIdx.x;
    __shared__ float sm[1024];

    float mv = -1e30f;
    for (int i = t; i < STREAMS; i += 1024) mv = fmaxf(mv, g_m[side][i]);
    sm[t] = mv;
    __syncthreads();
    for (int o = 512; o > 0; o >>= 1) {
        if (t < o) sm[t] = fmaxf(sm[t], sm[t + o]);
        __syncthreads();
    }
    float M = sm[0];
    __syncthreads();

    float z = 0.f;
    for (int i = t; i < STREAMS; i += 1024)
        z += g_z[side][i] * __expf(g_m[side][i] - M);
    sm[t] = z;
    __syncthreads();
    for (int o = 512; o > 0; o >>= 1) {
        if (t < o) sm[t] += sm[t + o];
        __syncthreads();
    }
    if (t == 0) { g_M[side] = M; g_Z[side] = sm[0]; }
}

// ---------------------------------------------------------
// Kernel 5: combine stream accumulators -> per-streamgroup partials.
// grid (DDIM/256, SGROUPS, 2), 256 threads.
// ---------------------------------------------------------
__global__ void combine_partial() {
    const int side = blockIdx.z;
    const int sg   = blockIdx.y;
    const int j    = blockIdx.x * 256 + threadIdx.x;

    __shared__ float coef[SG_SZ];
    float M = g_M[side];
    coef[threadIdx.x] = __expf(g_m[side][sg * SG_SZ + threadIdx.x] - M);
    __syncthreads();

    float s = 0.f;
    for (int c = 0; c < SG_SZ; c++)
        s = fmaf(coef[c], g_acc[side][sg * SG_SZ + c][j], s);

    g_part[side][sg][j] = s;
}

// ---------------------------------------------------------
// Kernel 6: final reduce over stream groups, normalize, write out.
// out layout: [0..2047] = left result, [2048..4095] = right.
// ---------------------------------------------------------
__global__ void combine_final(float* __restrict__ out) {
    const int side = blockIdx.y;
    const int j = blockIdx.x * 256 + threadIdx.x;
    float s = 0.f;
#pragma unroll
    for (int sg = 0; sg < SGROUPS; sg++) s += g_part[side][sg][j];
    out[side * DDIM + j] = s / g_Z[side];
}

// ---------------------------------------------------------
extern "C" void kernel_launch(void* const* d_in, const int* in_sizes, int n_in,
                              void* d_out, int out_size) {
    const float* wl    = (const float*)d_in[0];  // embed_word_l  [1, D]
    const float* wr    = (const float*)d_in[1];  // embed_word_r  [1, D]
    const float* candL = (const float*)d_in[2];  // embed_candidates_l [N, D]
    const float* candR = (const float*)d_in[3];  // embed_candidates_r [N, D]
    const float* Wa    = (const float*)d_in[4];  // W_a [D, D]
    const float* ba    = (const float*)d_in[5];  // b_a [1, D]
    float* out = (float*)d_out;

    align_partial<<<ALIGN_BLKS, 256>>>(wl, wr, Wa);
    align_finalize<<<DDIM / 256, 256>>>(ba);
    attn_fused<<<dim3(BLKS_PER_SIDE, 2), 256>>>(candL, candR);
    softmax_stats<<<2, 1024>>>();
    combine_partial<<<dim3(DDIM / 256, SGROUPS, 2), 256>>>();
    combine_final<<<dim3(DDIM / 256, 2), 256>>>(out);
}

// round 3
// speedup vs baseline: 1.4376x; 1.0952x over previous
#include <cuda_runtime.h>
#include <math.h>

#define DDIM 2048
#define NROWS 65536
#define RPB 128                       // rows per block (attn)
#define BLKS_PER_SIDE (NROWS / RPB)   // 512
#define WARPS_PB 8
#define RPW (RPB / WARPS_PB)          // 16 rows per warp-stream
#define ALIGN_BLKS 128
#define ALIGN_ROWS (DDIM / ALIGN_BLKS)  // 16

// -------- device scratch (no allocations allowed) --------
__device__ float g_align_part[ALIGN_BLKS][2][DDIM];     // 2 MB
__device__ float g_align[2][DDIM];
__device__ float g_acc[2][BLKS_PER_SIDE][DDIM];         // 8 MB
__device__ float g_m[2][BLKS_PER_SIDE];
__device__ float g_z[2][BLKS_PER_SIDE];

// ---------------------------------------------------------
// Kernel 1: partial GEMV for both sides against shared W_a.
// ---------------------------------------------------------
__global__ void align_partial(const float* __restrict__ wl,
                              const float* __restrict__ wr,
                              const float* __restrict__ Wa) {
    int b = blockIdx.x;
    int t = threadIdx.x;
    float accl[8], accr[8];
#pragma unroll
    for (int k = 0; k < 8; k++) { accl[k] = 0.f; accr[k] = 0.f; }

    int r0 = b * ALIGN_ROWS;
    for (int i = 0; i < ALIGN_ROWS; i++) {
        int row = r0 + i;
        float vl = wl[row];
        float vr = wr[row];
        const float* Wrow = Wa + (size_t)row * DDIM;
#pragma unroll
        for (int k = 0; k < 8; k++) {
            float w = Wrow[t + 256 * k];
            accl[k] = fmaf(vl, w, accl[k]);
            accr[k] = fmaf(vr, w, accr[k]);
        }
    }
#pragma unroll
    for (int k = 0; k < 8; k++) {
        g_align_part[b][0][t + 256 * k] = accl[k];
        g_align_part[b][1][t + 256 * k] = accr[k];
    }
}

// ---------------------------------------------------------
// Kernel 2: reduce align partials, add bias, tanh.
// ---------------------------------------------------------
__global__ void align_finalize(const float* __restrict__ ba) {
    int j = blockIdx.x * blockDim.x + threadIdx.x;
    float bias = ba[j];
    float sl = bias, sr = bias;
    for (int b = 0; b < ALIGN_BLKS; b++) {
        sl += g_align_part[b][0][j];
        sr += g_align_part[b][1][j];
    }
    g_align[0][j] = tanhf(sl);
    g_align[1][j] = tanhf(sr);
}

// ---------------------------------------------------------
// Kernel 3: fused score + online-softmax + weighted accumulate.
// Each warp owns 16 complete rows with a private online-softmax
// state; row loads are double-buffered in registers so 16 LDG.128
// stay in flight during compute. Epilogue merges the 8 warp
// states into one block state (rescale to block max, smem reduce).
// ---------------------------------------------------------
__global__ void __launch_bounds__(256, 1)
attn_fused(const float* __restrict__ candL, const float* __restrict__ candR) {
    const int side = blockIdx.y;                  // 0: left word vs candR
    const float* cand = (side == 0) ? candR : candL;
    const int blk  = blockIdx.x;
    const int warp = threadIdx.x >> 5;
    const int lane = threadIdx.x & 31;

    __shared__ float s_align[DDIM];               // 8 KB
    __shared__ float s_acc[WARPS_PB][DDIM];       // 64 KB
    __shared__ float s_m[WARPS_PB], s_z[WARPS_PB];

    for (int i = threadIdx.x; i < DDIM; i += 256)
        s_align[i] = g_align[side][i];
    __syncthreads();

    const float4* al = reinterpret_cast<const float4*>(s_align) + lane;

    float4 acc[16];
#pragma unroll
    for (int c = 0; c < 16; c++) acc[c] = make_float4(0.f, 0.f, 0.f, 0.f);
    float m = -1e30f, Z = 0.f;

    const int row0 = blk * RPB + warp * RPW;
    const float4* rbase =
        reinterpret_cast<const float4*>(cand + (size_t)row0 * DDIM) + lane;

    float4 xbuf[2][16];
#pragma unroll
    for (int c = 0; c < 16; c++) xbuf[0][c] = rbase[c * 32];

#pragma unroll
    for (int r = 0; r < RPW; r++) {
        float4* x  = xbuf[r & 1];
        float4* xn = xbuf[(r + 1) & 1];
        if (r + 1 < RPW) {
            const float4* rpn = rbase + (size_t)(r + 1) * (DDIM / 4);
#pragma unroll
            for (int c = 0; c < 16; c++) xn[c] = rpn[c * 32];
        }

        float p0 = 0.f, p1 = 0.f, p2 = 0.f, p3 = 0.f;
#pragma unroll
        for (int c = 0; c < 16; c++) {
            float4 a = al[c * 32];
            p0 = fmaf(x[c].x, a.x, p0);
            p1 = fmaf(x[c].y, a.y, p1);
            p2 = fmaf(x[c].z, a.z, p2);
            p3 = fmaf(x[c].w, a.w, p3);
        }
        float p = (p0 + p1) + (p2 + p3);
#pragma unroll
        for (int o = 16; o > 0; o >>= 1)
            p += __shfl_xor_sync(0xffffffffu, p, o);

        if (p > m) {
            float c = __expf(m - p);   // first row: exp(-huge) == 0
            Z *= c;
#pragma unroll
            for (int k = 0; k < 16; k++) {
                acc[k].x *= c; acc[k].y *= c; acc[k].z *= c; acc[k].w *= c;
            }
            m = p;
        }
        float w = __expf(p - m);
        Z += w;
#pragma unroll
        for (int k = 0; k < 16; k++) {
            acc[k].x = fmaf(w, x[k].x, acc[k].x);
            acc[k].y = fmaf(w, x[k].y, acc[k].y);
            acc[k].z = fmaf(w, x[k].z, acc[k].z);
            acc[k].w = fmaf(w, x[k].w, acc[k].w);
        }
    }

    // ---- block-level merge of the 8 warp states ----
    if (lane == 0) { s_m[warp] = m; s_z[warp] = Z; }
    __syncthreads();

    float mb = s_m[0];
#pragma unroll
    for (int w = 1; w < WARPS_PB; w++) mb = fmaxf(mb, s_m[w]);
    float scale = __expf(m - mb);      // warp-uniform

    float4* sa = reinterpret_cast<float4*>(&s_acc[warp][0]) + lane;
#pragma unroll
    for (int c = 0; c < 16; c++) {
        float4 v = acc[c];
        v.x *= scale; v.y *= scale; v.z *= scale; v.w *= scale;
        sa[c * 32] = v;
    }
    __syncthreads();

    for (int j = threadIdx.x; j < DDIM; j += 256) {
        float s = 0.f;
#pragma unroll
        for (int w = 0; w < WARPS_PB; w++) s += s_acc[w][j];
        g_acc[side][blk][j] = s;
    }
    if (threadIdx.x == 0) {
        float zb = 0.f;
#pragma unroll
        for (int w = 0; w < WARPS_PB; w++)
            zb += s_z[w] * __expf(s_m[w] - mb);
        g_m[side][blk] = mb;
        g_z[side][blk] = zb;
    }
}

// ---------------------------------------------------------
// Kernel 4: fused stats + combine. grid (DDIM/128, 2), 1024 thr.
// Each block redundantly reduces the 512 (m,z) pairs (2 KB, L2
// broadcast), then covers 128 output columns with the 512-chunk
// reduction split 8 ways across threadIdx/128.
// out layout: [0..2047] = left result, [2048..4095] = right.
// ---------------------------------------------------------
__global__ void __launch_bounds__(1024, 1)
finalize_out(float* __restrict__ out) {
    const int side = blockIdx.y;
    const int t = threadIdx.x;
    const int tj = t & 127;            // column within block
    const int tc = t >> 7;             // chunk partition 0..7

    __shared__ float s_coef[BLKS_PER_SIDE];
    __shared__ float s_red[512];
    __shared__ float s_part[8][128];

    // block max over 512 chunk maxima
    float mv = (t < BLKS_PER_SIDE) ? g_m[side][t] : -1e30f;
    if (t < 512) s_red[t] = mv;
    __syncthreads();
    for (int o = 256; o > 0; o >>= 1) {
        if (t < o) s_red[t] = fmaxf(s_red[t], s_red[t + o]);
        __syncthreads();
    }
    float M = s_red[0];
    __syncthreads();

    // coefficients and normalizer
    float zv = 0.f;
    if (t < BLKS_PER_SIDE) {
        float c = __expf(g_m[side][t] - M);
        s_coef[t] = c;
        zv = g_z[side][t] * c;
    }
    if (t < 512) s_red[t] = zv;
    __syncthreads();
    for (int o = 256; o > 0; o >>= 1) {
        if (t < o) s_red[t] += s_red[t + o];
        __syncthreads();
    }
    float Zi = 1.0f / s_red[0];

    // partial reduction over this partition's 64 chunks
    const int j = blockIdx.x * 128 + tj;
    float s = 0.f;
#pragma unroll 8
    for (int c = tc * 64; c < tc * 64 + 64; c++)
        s = fmaf(s_coef[c], g_acc[side][c][j], s);
    s_part[tc][tj] = s;
    __syncthreads();

    if (tc == 0) {
        float tot = 0.f;
#pragma unroll
        for (int k = 0; k < 8; k++) tot += s_part[k][tj];
        out[side * DDIM + j] = tot * Zi;
    }
}

// ---------------------------------------------------------
extern "C" void kernel_launch(void* const* d_in, const int* in_sizes, int n_in,
                              void* d_out, int out_size) {
    const float* wl    = (const float*)d_in[0];  // embed_word_l  [1, D]
    const float* wr    = (const float*)d_in[1];  // embed_word_r  [1, D]
    const float* candL = (const float*)d_in[2];  // embed_candidates_l [N, D]
    const float* candR = (const float*)d_in[3];  // embed_candidates_r [N, D]
    const float* Wa    = (const float*)d_in[4];  // W_a [D, D]
    const float* ba    = (const float*)d_in[5];  // b_a [1, D]
    float* out = (float*)d_out;

    align_partial<<<ALIGN_BLKS, 256>>>(wl, wr, Wa);
    align_finalize<<<DDIM / 256, 256>>>(ba);
    attn_fused<<<dim3(BLKS_PER_SIDE, 2), 256>>>(candL, candR);
    finalize_out<<<dim3(DDIM / 128, 2), 1024>>>(out);
}

// round 4
// speedup vs baseline: 1.6309x; 1.1345x over previous
#include <cuda_runtime.h>
#include <math.h>
#include <stdint.h>

#define DDIM 2048
#define NROWS 65536
#define RPB 128                        // rows per block (attn)
#define BLKS_PER_SIDE (NROWS / RPB)    // 512
#define WARPS_PB 8
#define NSTAGES 3
#define ROWS_PER_STAGE 8               // one row per warp per stage
#define STAGE_BYTES (ROWS_PER_STAGE * DDIM * 4)   // 65536
#define NUM_STAGES_TOTAL (RPB / ROWS_PER_STAGE)   // 16
#define ALIGN_BLKS 128
#define ALIGN_ROWS (DDIM / ALIGN_BLKS) // 16

// -------- device scratch (no allocations allowed) --------
__device__ float g_align_part[ALIGN_BLKS][2][DDIM];     // 2 MB
__device__ float g_align[2][DDIM];
__device__ float g_acc[2][BLKS_PER_SIDE][DDIM];         // 8 MB
__device__ float g_m[2][BLKS_PER_SIDE];
__device__ float g_z[2][BLKS_PER_SIDE];

// -------- PTX helpers --------
__device__ __forceinline__ uint32_t smem_u32(const void* p) {
    return (uint32_t)__cvta_generic_to_shared(p);
}
#define MBAR_INIT(addr, cnt) \
    asm volatile("mbarrier.init.shared.b64 [%0], %1;" :: "r"(addr), "r"(cnt) : "memory")
#define MBAR_EXPECT_TX(addr, bytes) \
    asm volatile("mbarrier.arrive.expect_tx.shared.b64 _, [%0], %1;" :: "r"(addr), "r"(bytes) : "memory")
#define BULK_G2S(dst, src, bytes, mbar) \
    asm volatile("cp.async.bulk.shared::cta.global.mbarrier::complete_tx::bytes [%0], [%1], %2, [%3];" \
                 :: "r"(dst), "l"(src), "r"(bytes), "r"(mbar) : "memory")
#define MBAR_WAIT_PARITY(addr, parity) do {                                        \
    uint32_t _m = (addr); uint32_t _p = (parity); uint32_t _done;                  \
    asm volatile("{\n\t.reg .pred p;\n\t"                                          \
        "mbarrier.try_wait.parity.acquire.cta.shared::cta.b64 p, [%1], %2;\n\t"    \
        "selp.b32 %0, 1, 0, p;\n\t}"                                               \
        : "=r"(_done) : "r"(_m), "r"(_p) : "memory");                              \
    if (!_done) {                                                                  \
        asm volatile("{\n\t.reg .pred P1;\n\t"                                     \
            "WL_%=:\n\t"                                                           \
            "mbarrier.try_wait.parity.acquire.cta.shared::cta.b64 P1, [%0], %1, 0x989680;\n\t" \
            "@P1 bra.uni WD_%=;\n\t"                                               \
            "bra.uni WL_%=;\n\t"                                                   \
            "WD_%=:\n\t}" :: "r"(_m), "r"(_p) : "memory");                         \
    }                                                                              \
} while (0)

// ---------------------------------------------------------
// Kernel 1: partial GEMV for both sides against shared W_a.
// ---------------------------------------------------------
__global__ void align_partial(const float* __restrict__ wl,
                              const float* __restrict__ wr,
                              const float* __restrict__ Wa) {
    int b = blockIdx.x;
    int t = threadIdx.x;
    float accl[8], accr[8];
#pragma unroll
    for (int k = 0; k < 8; k++) { accl[k] = 0.f; accr[k] = 0.f; }

    int r0 = b * ALIGN_ROWS;
    for (int i = 0; i < ALIGN_ROWS; i++) {
        int row = r0 + i;
        float vl = wl[row];
        float vr = wr[row];
        const float* Wrow = Wa + (size_t)row * DDIM;
#pragma unroll
        for (int k = 0; k < 8; k++) {
            float w = Wrow[t + 256 * k];
            accl[k] = fmaf(vl, w, accl[k]);
            accr[k] = fmaf(vr, w, accr[k]);
        }
    }
#pragma unroll
    for (int k = 0; k < 8; k++) {
        g_align_part[b][0][t + 256 * k] = accl[k];
        g_align_part[b][1][t + 256 * k] = accr[k];
    }
}

// ---------------------------------------------------------
// Kernel 2: reduce align partials, add bias, tanh.
// ---------------------------------------------------------
__global__ void align_finalize(const float* __restrict__ ba) {
    int j = blockIdx.x * blockDim.x + threadIdx.x;
    float bias = ba[j];
    float sl = bias, sr = bias;
    for (int b = 0; b < ALIGN_BLKS; b++) {
        sl += g_align_part[b][0][j];
        sr += g_align_part[b][1][j];
    }
    g_align[0][j] = tanhf(sl);
    g_align[1][j] = tanhf(sr);
}

// ---------------------------------------------------------
// Kernel 3: fused score + online-softmax + weighted accumulate.
// TMA (cp.async.bulk) 3-deep smem ring: stage = 8 contiguous rows
// (64 KB), one mbarrier per slot, __syncthreads per stage gates
// slot reuse. Warp w consumes row w of each stage from smem and
// keeps a private online-softmax state; the 8 warp states merge
// through the ring smem (reused) at the end.
// ---------------------------------------------------------
extern __shared__ float dynsmem[];     // NSTAGES * 64 KB ring; reused as merge buf

__global__ void __launch_bounds__(256, 1)
attn_fused(const float* __restrict__ candL, const float* __restrict__ candR) {
    const int side = blockIdx.y;                  // 0: left word vs candR
    const float* cand = (side == 0) ? candR : candL;
    const int blk  = blockIdx.x;
    const int tid  = threadIdx.x;
    const int warp = tid >> 5;
    const int lane = tid & 31;

    __shared__ float s_align[DDIM];               // 8 KB
    __shared__ float s_m[WARPS_PB], s_z[WARPS_PB];
    __shared__ uint64_t s_mbar[NSTAGES];

    for (int i = tid; i < DDIM; i += 256)
        s_align[i] = g_align[side][i];

    if (tid == 0) {
#pragma unroll
        for (int s = 0; s < NSTAGES; s++)
            MBAR_INIT(smem_u32(&s_mbar[s]), 1);
    }
    __syncthreads();

    // cache align slice in registers: lane l owns cols {4l + 128c}
    float4 al[16];
    {
        const float4* ap = reinterpret_cast<const float4*>(s_align) + lane;
#pragma unroll
        for (int c = 0; c < 16; c++) al[c] = ap[c * 32];
    }

    const float* gbase = cand + (size_t)blk * RPB * DDIM;

    // prologue: fetch stages 0..2
    if (tid == 0) {
#pragma unroll
        for (int s = 0; s < NSTAGES; s++) {
            uint32_t mb = smem_u32(&s_mbar[s]);
            MBAR_EXPECT_TX(mb, STAGE_BYTES);
            uint32_t dst = smem_u32(dynsmem) + s * STAGE_BYTES;
            BULK_G2S(dst, gbase + (size_t)s * ROWS_PER_STAGE * DDIM,
                     STAGE_BYTES, mb);
        }
    }

    float4 acc[16];
#pragma unroll
    for (int c = 0; c < 16; c++) acc[c] = make_float4(0.f, 0.f, 0.f, 0.f);
    float m = -1e30f, Z = 0.f;

    for (int s = 0; s < NUM_STAGES_TOTAL; s++) {
        const int slot = s % NSTAGES;
        MBAR_WAIT_PARITY(smem_u32(&s_mbar[slot]), (s / NSTAGES) & 1);

        const float4* rp = reinterpret_cast<const float4*>(
            dynsmem + slot * (STAGE_BYTES / 4) + warp * DDIM) + lane;

        float4 x[16];
#pragma unroll
        for (int c = 0; c < 16; c++) x[c] = rp[c * 32];

        float p0 = 0.f, p1 = 0.f, p2 = 0.f, p3 = 0.f;
#pragma unroll
        for (int c = 0; c < 16; c++) {
            p0 = fmaf(x[c].x, al[c].x, p0);
            p1 = fmaf(x[c].y, al[c].y, p1);
            p2 = fmaf(x[c].z, al[c].z, p2);
            p3 = fmaf(x[c].w, al[c].w, p3);
        }
        float p = (p0 + p1) + (p2 + p3);
#pragma unroll
        for (int o = 16; o > 0; o >>= 1)
            p += __shfl_xor_sync(0xffffffffu, p, o);

        if (p > m) {
            float c = __expf(m - p);   // first row: exp(-huge) == 0
            Z *= c;
#pragma unroll
            for (int k = 0; k < 16; k++) {
                acc[k].x *= c; acc[k].y *= c; acc[k].z *= c; acc[k].w *= c;
            }
            m = p;
        }
        float w = __expf(p - m);
        Z += w;
#pragma unroll
        for (int k = 0; k < 16; k++) {
            acc[k].x = fmaf(w, x[k].x, acc[k].x);
            acc[k].y = fmaf(w, x[k].y, acc[k].y);
            acc[k].z = fmaf(w, x[k].z, acc[k].z);
            acc[k].w = fmaf(w, x[k].w, acc[k].w);
        }

        __syncthreads();               // all warps done with this slot
        if (tid == 0 && s + NSTAGES < NUM_STAGES_TOTAL) {
            int sn = s + NSTAGES;
            uint32_t mb = smem_u32(&s_mbar[slot]);
            MBAR_EXPECT_TX(mb, STAGE_BYTES);
            uint32_t dst = smem_u32(dynsmem) + slot * STAGE_BYTES;
            BULK_G2S(dst, gbase + (size_t)sn * ROWS_PER_STAGE * DDIM,
                     STAGE_BYTES, mb);
        }
    }

    // ---- block-level merge of the 8 warp states (ring smem reused) ----
    if (lane == 0) { s_m[warp] = m; s_z[warp] = Z; }
    __syncthreads();

    float mb2 = s_m[0];
#pragma unroll
    for (int w = 1; w < WARPS_PB; w++) mb2 = fmaxf(mb2, s_m[w]);
    float scale = __expf(m - mb2);     // warp-uniform

    float* s_acc = dynsmem;            // [WARPS_PB][DDIM], 64 KB of the ring
    float4* sa = reinterpret_cast<float4*>(s_acc + warp * DDIM) + lane;
#pragma unroll
    for (int c = 0; c < 16; c++) {
        float4 v = acc[c];
        v.x *= scale; v.y *= scale; v.z *= scale; v.w *= scale;
        sa[c * 32] = v;
    }
    __syncthreads();

    for (int j = tid; j < DDIM; j += 256) {
        float ssum = 0.f;
#pragma unroll
        for (int w = 0; w < WARPS_PB; w++) ssum += s_acc[w * DDIM + j];
        g_acc[side][blk][j] = ssum;
    }
    if (tid == 0) {
        float zb = 0.f;
#pragma unroll
        for (int w = 0; w < WARPS_PB; w++)
            zb += s_z[w] * __expf(s_m[w] - mb2);
        g_m[side][blk] = mb2;
        g_z[side][blk] = zb;
    }
}

// ---------------------------------------------------------
// Kernel 4: fused stats + combine. grid (DDIM/128, 2), 1024 thr.
// out layout: [0..2047] = left result, [2048..4095] = right.
// ---------------------------------------------------------
__global__ void __launch_bounds__(1024, 1)
finalize_out(float* __restrict__ out) {
    const int side = blockIdx.y;
    const int t = threadIdx.x;
    const int tj = t & 127;            // column within block
    const int tc = t >> 7;             // chunk partition 0..7

    __shared__ float s_coef[BLKS_PER_SIDE];
    __shared__ float s_red[512];
    __shared__ float s_part[8][128];

    float mv = (t < BLKS_PER_SIDE) ? g_m[side][t] : -1e30f;
    if (t < 512) s_red[t] = mv;
    __syncthreads();
    for (int o = 256; o > 0; o >>= 1) {
        if (t < o) s_red[t] = fmaxf(s_red[t], s_red[t + o]);
        __syncthreads();
    }
    float M = s_red[0];
    __syncthreads();

    float zv = 0.f;
    if (t < BLKS_PER_SIDE) {
        float c = __expf(g_m[side][t] - M);
        s_coef[t] = c;
        zv = g_z[side][t] * c;
    }
    if (t < 512) s_red[t] = zv;
    __syncthreads();
    for (int o = 256; o > 0; o >>= 1) {
        if (t < o) s_red[t] += s_red[t + o];
        __syncthreads();
    }
    float Zi = 1.0f / s_red[0];

    const int j = blockIdx.x * 128 + tj;
    float s = 0.f;
#pragma unroll 8
    for (int c = tc * 64; c < tc * 64 + 64; c++)
        s = fmaf(s_coef[c], g_acc[side][c][j], s);
    s_part[tc][tj] = s;
    __syncthreads();

    if (tc == 0) {
        float tot = 0.f;
#pragma unroll
        for (int k = 0; k < 8; k++) tot += s_part[k][tj];
        out[side * DDIM + j] = tot * Zi;
    }
}

// ---------------------------------------------------------
extern "C" void kernel_launch(void* const* d_in, const int* in_sizes, int n_in,
                              void* d_out, int out_size) {
    const float* wl    = (const float*)d_in[0];  // embed_word_l  [1, D]
    const float* wr    = (const float*)d_in[1];  // embed_word_r  [1, D]
    const float* candL = (const float*)d_in[2];  // embed_candidates_l [N, D]
    const float* candR = (const float*)d_in[3];  // embed_candidates_r [N, D]
    const float* Wa    = (const float*)d_in[4];  // W_a [D, D]
    const float* ba    = (const float*)d_in[5];  // b_a [1, D]
    float* out = (float*)d_out;

    static int smem_set = 0;   // idempotent attribute set (not a guard on work)
    if (!smem_set) {
        cudaFuncSetAttribute(attn_fused,
                             cudaFuncAttributeMaxDynamicSharedMemorySize,
                             NSTAGES * STAGE_BYTES);
        smem_set = 1;
    }

    align_partial<<<ALIGN_BLKS, 256>>>(wl, wr, Wa);
    align_finalize<<<DDIM / 256, 256>>>(ba);
    attn_fused<<<dim3(BLKS_PER_SIDE, 2), 256, NSTAGES * STAGE_BYTES>>>(candL, candR);
    finalize_out<<<dim3(DDIM / 128, 2), 1024>>>(out);
}